// round 1
// baseline (speedup 1.0000x reference)
#include <cuda_runtime.h>

#define NTOK 4096
#define DIM  1024
#define HID  2048
#define NEXP 8
#define KSEL 2
#define VOC  32000
#define LN_EPS 1e-5f

// ---------------- scratch (static device globals; no runtime alloc) ----------------
__device__ float g_h  [(size_t)NTOK * DIM];          // 16 MB  token embeddings
__device__ float g_a  [(size_t)NTOK * KSEL * HID];   // 64 MB  relu(h W1 + b1) per slot
__device__ float g_eo [(size_t)NTOK * KSEL * DIM];   // 32 MB  expert outputs per slot
__device__ float g_yn [(size_t)NTOK * DIM];          // 16 MB  layernormed combined
__device__ float g_tv [NTOK * KSEL];                 // top-k gate values
__device__ int   g_list[NEXP * NTOK];                // per-expert slot lists
__device__ int   g_count[NEXP];

// ---------------- kernel 0: reset routing counters ----------------
__global__ void reset_counts_kernel() {
    if (threadIdx.x < NEXP) g_count[threadIdx.x] = 0;
}

// ---------------- kernel 1: embed + gate softmax + top-2 + scatter ----------------
__global__ void embed_gate_kernel(const int* __restrict__ x,
                                  const float* __restrict__ embed_W,
                                  const float* __restrict__ gate_W,
                                  const float* __restrict__ gate_b,
                                  float* __restrict__ out, int write_idx) {
    __shared__ float sh[DIM];
    __shared__ float slogit[NEXP];
    const int n   = blockIdx.x;
    const int tid = threadIdx.x;
    const int tok = x[n];
    const float* erow = embed_W + (size_t)tok * DIM;
    float* hrow = g_h + (size_t)n * DIM;
    #pragma unroll
    for (int q = 0; q < DIM / 256; ++q) {
        int d = tid + q * 256;
        float v = erow[d];
        sh[d] = v;
        hrow[d] = v;
    }
    __syncthreads();
    const int w = tid >> 5, lane = tid & 31;   // 8 warps == 8 experts
    const float* gw = gate_W + (size_t)w * DIM;
    float acc = 0.f;
    for (int d = lane; d < DIM; d += 32) acc = fmaf(sh[d], gw[d], acc);
    #pragma unroll
    for (int o = 16; o > 0; o >>= 1) acc += __shfl_xor_sync(0xffffffffu, acc, o);
    if (lane == 0) slogit[w] = acc + gate_b[w];
    __syncthreads();
    if (tid == 0) {
        float mx = slogit[0];
        #pragma unroll
        for (int e = 1; e < NEXP; ++e) mx = fmaxf(mx, slogit[e]);
        float p[NEXP]; float s = 0.f;
        #pragma unroll
        for (int e = 0; e < NEXP; ++e) { p[e] = expf(slogit[e] - mx); s += p[e]; }
        float inv = 1.f / s;
        #pragma unroll
        for (int e = 0; e < NEXP; ++e) p[e] *= inv;
        // top-1 (earliest index wins ties, matching lax.top_k)
        int i0 = 0; float v0 = p[0];
        #pragma unroll
        for (int e = 1; e < NEXP; ++e) if (p[e] > v0) { v0 = p[e]; i0 = e; }
        // top-2
        int i1 = -1; float v1 = -1.f;
        #pragma unroll
        for (int e = 0; e < NEXP; ++e) {
            if (e == i0) continue;
            if (p[e] > v1) { v1 = p[e]; i1 = e; }
        }
        g_tv[n * 2 + 0] = v0;
        g_tv[n * 2 + 1] = v1;
        int pos0 = atomicAdd(&g_count[i0], 1);
        g_list[i0 * NTOK + pos0] = n * 2;
        int pos1 = atomicAdd(&g_count[i1], 1);
        g_list[i1 * NTOK + pos1] = n * 2 + 1;
        if (write_idx) {
            out[(size_t)NTOK * VOC + n * 2 + 0] = (float)i0;
            out[(size_t)NTOK * VOC + n * 2 + 1] = (float)i1;
        }
    }
}

// ---------------- kernel 2: expert GEMM1  a[slot] = relu(h W1[e] + b1[e]) ----------------
// 128x128x16 tile, 256 threads, 8x8 micro; rows gathered via per-expert list.
__global__ void expert_gemm1_kernel(const float* __restrict__ W1,
                                    const float* __restrict__ b1) {
    const int e = blockIdx.z;
    const int cnt = g_count[e];
    const int rowBase = blockIdx.y * 128;
    if (rowBase >= cnt) return;
    const int colBase = blockIdx.x * 128;
    const float* Bm = W1 + (size_t)e * DIM * HID;

    __shared__ float As[16][128];
    __shared__ float Bs[16][128];
    __shared__ int   rows[128];
    const int tid = threadIdx.x;
    if (tid < 128) {
        int r = rowBase + tid;
        rows[tid] = (r < cnt) ? g_list[e * NTOK + r] : -1;
    }
    __syncthreads();

    float acc[8][8];
    #pragma unroll
    for (int i = 0; i < 8; ++i)
        #pragma unroll
        for (int j = 0; j < 8; ++j) acc[i][j] = 0.f;

    const int a_k4 = (tid & 3) * 4;
    const int a_m  = tid >> 2;
    const int b_n4 = (tid & 31) * 4;
    const int b_k  = tid >> 5;
    const int tm = (tid >> 4) * 8;
    const int tn = (tid & 15) * 8;

    for (int k0 = 0; k0 < DIM; k0 += 16) {
        #pragma unroll
        for (int p = 0; p < 2; ++p) {
            int m = a_m + p * 64;
            int slot = rows[m];
            float4 v = make_float4(0.f, 0.f, 0.f, 0.f);
            if (slot >= 0)
                v = *(const float4*)(g_h + (size_t)(slot >> 1) * DIM + k0 + a_k4);
            As[a_k4 + 0][m] = v.x; As[a_k4 + 1][m] = v.y;
            As[a_k4 + 2][m] = v.z; As[a_k4 + 3][m] = v.w;
        }
        #pragma unroll
        for (int p = 0; p < 2; ++p) {
            int k = b_k + p * 8;
            *(float4*)&Bs[k][b_n4] =
                *(const float4*)(Bm + (size_t)(k0 + k) * HID + colBase + b_n4);
        }
        __syncthreads();
        #pragma unroll
        for (int kk = 0; kk < 16; ++kk) {
            float a[8], b[8];
            *(float4*)&a[0] = *(const float4*)&As[kk][tm];
            *(float4*)&a[4] = *(const float4*)&As[kk][tm + 4];
            *(float4*)&b[0] = *(const float4*)&Bs[kk][tn];
            *(float4*)&b[4] = *(const float4*)&Bs[kk][tn + 4];
            #pragma unroll
            for (int i = 0; i < 8; ++i)
                #pragma unroll
                for (int j = 0; j < 8; ++j)
                    acc[i][j] = fmaf(a[i], b[j], acc[i][j]);
        }
        __syncthreads();
    }
    const float* bias = b1 + (size_t)e * HID + colBase;
    #pragma unroll
    for (int i = 0; i < 8; ++i) {
        int slot = rows[tm + i];
        if (slot < 0) continue;
        float* op = g_a + (size_t)slot * HID + colBase + tn;
        #pragma unroll
        for (int j = 0; j < 8; ++j) {
            float v = acc[i][j] + bias[tn + j];
            op[j] = v > 0.f ? v : 0.f;
        }
    }
}

// ---------------- kernel 3: expert GEMM2  eo[slot] = a[slot] W2[e] + b2[e] ----------------
__global__ void expert_gemm2_kernel(const float* __restrict__ W2,
                                    const float* __restrict__ b2) {
    const int e = blockIdx.z;
    const int cnt = g_count[e];
    const int rowBase = blockIdx.y * 128;
    if (rowBase >= cnt) return;
    const int colBase = blockIdx.x * 128;
    const float* Bm = W2 + (size_t)e * HID * DIM;

    __shared__ float As[16][128];
    __shared__ float Bs[16][128];
    __shared__ int   rows[128];
    const int tid = threadIdx.x;
    if (tid < 128) {
        int r = rowBase + tid;
        rows[tid] = (r < cnt) ? g_list[e * NTOK + r] : -1;
    }
    __syncthreads();

    float acc[8][8];
    #pragma unroll
    for (int i = 0; i < 8; ++i)
        #pragma unroll
        for (int j = 0; j < 8; ++j) acc[i][j] = 0.f;

    const int a_k4 = (tid & 3) * 4;
    const int a_m  = tid >> 2;
    const int b_n4 = (tid & 31) * 4;
    const int b_k  = tid >> 5;
    const int tm = (tid >> 4) * 8;
    const int tn = (tid & 15) * 8;

    for (int k0 = 0; k0 < HID; k0 += 16) {
        #pragma unroll
        for (int p = 0; p < 2; ++p) {
            int m = a_m + p * 64;
            int slot = rows[m];
            float4 v = make_float4(0.f, 0.f, 0.f, 0.f);
            if (slot >= 0)
                v = *(const float4*)(g_a + (size_t)slot * HID + k0 + a_k4);
            As[a_k4 + 0][m] = v.x; As[a_k4 + 1][m] = v.y;
            As[a_k4 + 2][m] = v.z; As[a_k4 + 3][m] = v.w;
        }
        #pragma unroll
        for (int p = 0; p < 2; ++p) {
            int k = b_k + p * 8;
            *(float4*)&Bs[k][b_n4] =
                *(const float4*)(Bm + (size_t)(k0 + k) * DIM + colBase + b_n4);
        }
        __syncthreads();
        #pragma unroll
        for (int kk = 0; kk < 16; ++kk) {
            float a[8], b[8];
            *(float4*)&a[0] = *(const float4*)&As[kk][tm];
            *(float4*)&a[4] = *(const float4*)&As[kk][tm + 4];
            *(float4*)&b[0] = *(const float4*)&Bs[kk][tn];
            *(float4*)&b[4] = *(const float4*)&Bs[kk][tn + 4];
            #pragma unroll
            for (int i = 0; i < 8; ++i)
                #pragma unroll
                for (int j = 0; j < 8; ++j)
                    acc[i][j] = fmaf(a[i], b[j], acc[i][j]);
        }
        __syncthreads();
    }
    const float* bias = b2 + (size_t)e * DIM + colBase;
    #pragma unroll
    for (int i = 0; i < 8; ++i) {
        int slot = rows[tm + i];
        if (slot < 0) continue;
        float* op = g_eo + (size_t)slot * DIM + colBase + tn;
        #pragma unroll
        for (int j = 0; j < 8; ++j)
            op[j] = acc[i][j] + bias[tn + j];
    }
}

// ---------------- kernel 4: combine gates + LayerNorm ----------------
__global__ void combine_ln_kernel(const float* __restrict__ ln_g,
                                  const float* __restrict__ ln_b) {
    const int n = blockIdx.x;
    const int tid = threadIdx.x;
    const float* e0 = g_eo + (size_t)n * 2 * DIM;
    const float* e1 = e0 + DIM;
    const float tv0 = g_tv[n * 2 + 0];
    const float tv1 = g_tv[n * 2 + 1];
    float y[DIM / 256];
    float s = 0.f, ss = 0.f;
    #pragma unroll
    for (int q = 0; q < DIM / 256; ++q) {
        int d = tid + q * 256;
        float v = fmaf(tv0, e0[d], tv1 * e1[d]);
        y[q] = v;
        s += v; ss = fmaf(v, v, ss);
    }
    __shared__ float rs[8], rss[8];
    #pragma unroll
    for (int o = 16; o > 0; o >>= 1) {
        s  += __shfl_xor_sync(0xffffffffu, s, o);
        ss += __shfl_xor_sync(0xffffffffu, ss, o);
    }
    const int w = tid >> 5, lane = tid & 31;
    if (lane == 0) { rs[w] = s; rss[w] = ss; }
    __syncthreads();
    if (w == 0) {
        s  = (lane < 8) ? rs[lane]  : 0.f;
        ss = (lane < 8) ? rss[lane] : 0.f;
        #pragma unroll
        for (int o = 4; o > 0; o >>= 1) {
            s  += __shfl_xor_sync(0xffffffffu, s, o);
            ss += __shfl_xor_sync(0xffffffffu, ss, o);
        }
        if (lane == 0) { rs[0] = s; rss[0] = ss; }
    }
    __syncthreads();
    const float mu  = rs[0] * (1.f / DIM);
    const float var = rss[0] * (1.f / DIM) - mu * mu;
    const float inv = rsqrtf(var + LN_EPS);
    float* yn = g_yn + (size_t)n * DIM;
    #pragma unroll
    for (int q = 0; q < DIM / 256; ++q) {
        int d = tid + q * 256;
        yn[d] = fmaf((y[q] - mu) * inv, ln_g[d], ln_b[d]);
    }
}

// ---------------- kernel 5: vocab head GEMM  logits = yn @ head_W^T + head_b ----------------
__global__ void head_gemm_kernel(const float* __restrict__ head_W,
                                 const float* __restrict__ head_b,
                                 float* __restrict__ out) {
    const int rowBase = blockIdx.y * 128;
    const int colBase = blockIdx.x * 128;
    __shared__ float As[16][128];
    __shared__ float Bs[16][128];
    const int tid = threadIdx.x;

    float acc[8][8];
    #pragma unroll
    for (int i = 0; i < 8; ++i)
        #pragma unroll
        for (int j = 0; j < 8; ++j) acc[i][j] = 0.f;

    const int a_k4 = (tid & 3) * 4;
    const int a_m  = tid >> 2;
    const int tm = (tid >> 4) * 8;
    const int tn = (tid & 15) * 8;

    for (int k0 = 0; k0 < DIM; k0 += 16) {
        #pragma unroll
        for (int p = 0; p < 2; ++p) {
            int m = a_m + p * 64;
            float4 v = *(const float4*)(g_yn + (size_t)(rowBase + m) * DIM + k0 + a_k4);
            As[a_k4 + 0][m] = v.x; As[a_k4 + 1][m] = v.y;
            As[a_k4 + 2][m] = v.z; As[a_k4 + 3][m] = v.w;
            // head_W is [VOC, DIM] row-major; logical B[k][n] = head_W[n][k]
            float4 wv = *(const float4*)(head_W + (size_t)(colBase + m) * DIM + k0 + a_k4);
            Bs[a_k4 + 0][m] = wv.x; Bs[a_k4 + 1][m] = wv.y;
            Bs[a_k4 + 2][m] = wv.z; Bs[a_k4 + 3][m] = wv.w;
        }
        __syncthreads();
        #pragma unroll
        for (int kk = 0; kk < 16; ++kk) {
            float a[8], b[8];
            *(float4*)&a[0] = *(const float4*)&As[kk][tm];
            *(float4*)&a[4] = *(const float4*)&As[kk][tm + 4];
            *(float4*)&b[0] = *(const float4*)&Bs[kk][tn];
            *(float4*)&b[4] = *(const float4*)&Bs[kk][tn + 4];
            #pragma unroll
            for (int i = 0; i < 8; ++i)
                #pragma unroll
                for (int j = 0; j < 8; ++j)
                    acc[i][j] = fmaf(a[i], b[j], acc[i][j]);
        }
        __syncthreads();
    }
    #pragma unroll
    for (int i = 0; i < 8; ++i) {
        float* op = out + (size_t)(rowBase + tm + i) * VOC + colBase + tn;
        #pragma unroll
        for (int j = 0; j < 8; ++j)
            op[j] = acc[i][j] + head_b[colBase + tn + j];
    }
}

// ---------------- launch ----------------
extern "C" void kernel_launch(void* const* d_in, const int* in_sizes, int n_in,
                              void* d_out, int out_size) {
    const int*   x       = (const int*)  d_in[0];
    const float* embed_W = (const float*)d_in[1];
    const float* gate_W  = (const float*)d_in[2];
    const float* gate_b  = (const float*)d_in[3];
    const float* W1      = (const float*)d_in[4];
    const float* b1      = (const float*)d_in[5];
    const float* W2      = (const float*)d_in[6];
    const float* b2      = (const float*)d_in[7];
    const float* ln_g    = (const float*)d_in[8];
    const float* ln_b    = (const float*)d_in[9];
    const float* head_W  = (const float*)d_in[10];
    const float* head_b  = (const float*)d_in[11];
    float* out = (float*)d_out;

    const long long need_idx = (long long)NTOK * VOC + (long long)NTOK * KSEL;
    int write_idx = ((long long)out_size >= need_idx) ? 1 : 0;

    reset_counts_kernel<<<1, 32>>>();
    embed_gate_kernel<<<NTOK, 256>>>(x, embed_W, gate_W, gate_b, out, write_idx);
    expert_gemm1_kernel<<<dim3(HID / 128, NTOK / 128, NEXP), 256>>>(W1, b1);
    expert_gemm2_kernel<<<dim3(DIM / 128, NTOK / 128, NEXP), 256>>>(W2, b2);
    combine_ln_kernel<<<NTOK, 256>>>(ln_g, ln_b);
    head_gemm_kernel<<<dim3(VOC / 128, NTOK / 128), 256>>>(head_W, head_b, out);
}